// round 1
// baseline (speedup 1.0000x reference)
#include <cuda_runtime.h>
#include <cstdint>

// Problem constants (Model_25855703122577):
//   inputs [8192, 784, 1] f32, W_ih [30,1], W_hh [30,30], b_mod [30],
//   W_lin [10,30], b_lin [10]  ->  out [8192, 10] f32
#define RB   8192    // batch
#define RT   784     // time steps
#define RH   30      // hidden
#define RC   10      // classes
#define GRP  8       // threads cooperating on one batch element
#define RPT  4       // rows (hidden units) per thread: 8*4=32 >= 30 (2 pad rows)
#define KP   15      // k-pairs: 30 = 15 * 2 (exact, no pad on k)
#define BPB  8       // batch elements per block
#define TPB  (BPB * GRP)   // 64 threads / block
#define HSTR 36      // smem floats per h slot (4-bank shift per group -> conflict-free)

// ---------------- packed f32x2 helpers (sm_100+) ----------------
__device__ __forceinline__ unsigned long long fmul2(unsigned long long a,
                                                    unsigned long long b) {
    unsigned long long d;
    asm("mul.rn.f32x2 %0, %1, %2;" : "=l"(d) : "l"(a), "l"(b));
    return d;
}
__device__ __forceinline__ unsigned long long ffma2(unsigned long long a,
                                                    unsigned long long b,
                                                    unsigned long long c) {
    unsigned long long d;
    asm("fma.rn.f32x2 %0, %1, %2, %3;" : "=l"(d) : "l"(a), "l"(b), "l"(c));
    return d;
}
__device__ __forceinline__ void unpack2(unsigned long long v, float& lo, float& hi) {
    asm("mov.b64 {%0, %1}, %2;" : "=f"(lo), "=f"(hi) : "l"(v));
}

// One recurrence step for this thread's 4 hidden rows.
// hsrc: smem base of this batch's full h vector (30 floats, b64-readable).
// hdst: smem address of this thread's 4-float slot in the *other* buffer.
__device__ __forceinline__ void rnn_step(
    float x,
    const unsigned long long (&w)[RPT][KP],
    const float (&wih)[RPT],
    const float (&bm)[RPT],
    const float* __restrict__ hsrc,
    float* __restrict__ hdst)
{
    // Load full h as 15 packed f32x2 (broadcast within group; groups 4 banks apart).
    unsigned long long h2[KP];
    const unsigned long long* hp = reinterpret_cast<const unsigned long long*>(hsrc);
#pragma unroll
    for (int p = 0; p < KP; p++) h2[p] = hp[p];

    float hv[RPT];
#pragma unroll
    for (int r = 0; r < RPT; r++) {
        unsigned long long acc = fmul2(w[r][0], h2[0]);
#pragma unroll
        for (int p = 1; p < KP; p++) acc = ffma2(w[r][p], h2[p], acc);
        float lo, hi;
        unpack2(acc, lo, hi);
        float z = fmaf(x, wih[r], lo + hi);          // + x * W_ih[row]
        // modReLU: sign(z) * relu(|z| + b); sign(0) == 0
        float m = fmaxf(fabsf(z) + bm[r], 0.0f);
        float s = copysignf(m, z);
        hv[r] = (z == 0.0f) ? 0.0f : s;
    }
    *reinterpret_cast<float4*>(hdst) = make_float4(hv[0], hv[1], hv[2], hv[3]);
    __syncwarp();   // groups are warp-internal: fences smem + orders buffers
}

extern "C" __global__ void __launch_bounds__(TPB)
rnn_modrelu_kernel(const float* __restrict__ inputs,  // [B, T]
                   const float* __restrict__ W_ih,    // [H]
                   const float* __restrict__ W_hh,    // [H, H] row-major
                   const float* __restrict__ b_mod,   // [H]
                   const float* __restrict__ W_lin,   // [C, H]
                   const float* __restrict__ b_lin,   // [C]
                   float* __restrict__ out)           // [B, C]
{
    __shared__ float hbuf[2][BPB][HSTR];

    const int tid = threadIdx.x;
    const int sub = tid & (GRP - 1);   // 0..7: which row-slice of h
    const int g   = tid >> 3;          // 0..7: batch element within block
    const int b   = blockIdx.x * BPB + g;

    // ---- load this thread's 4 weight rows into registers (packed over k) ----
    unsigned long long w[RPT][KP];
    float wih[RPT], bm[RPT];
#pragma unroll
    for (int r = 0; r < RPT; r++) {
        const int row = sub * RPT + r;
        if (row < RH) {
            // row*RH*4 bytes = 120*row: 8-byte aligned for every row
            const unsigned long long* wr =
                reinterpret_cast<const unsigned long long*>(W_hh + row * RH);
#pragma unroll
            for (int p = 0; p < KP; p++) w[r][p] = wr[p];
            wih[r] = W_ih[row];
            bm[r]  = b_mod[row];
        } else {  // pad rows 30,31: all-zero => z=0 => h stays exactly 0
#pragma unroll
            for (int p = 0; p < KP; p++) w[r][p] = 0ULL;
            wih[r] = 0.0f;
            bm[r]  = 0.0f;
        }
    }

    // h0 = 0 in buffer 0
    *reinterpret_cast<float4*>(&hbuf[0][g][sub * 4]) = make_float4(0, 0, 0, 0);
    __syncwarp();

    const float* xr = inputs + (size_t)b * RT;   // per-batch series is contiguous

#pragma unroll 1
    for (int t0 = 0; t0 < RT; t0 += 4) {
        const float4 x4 = *reinterpret_cast<const float4*>(xr + t0);
        rnn_step(x4.x, w, wih, bm, &hbuf[0][g][0], &hbuf[1][g][sub * 4]);
        rnn_step(x4.y, w, wih, bm, &hbuf[1][g][0], &hbuf[0][g][sub * 4]);
        rnn_step(x4.z, w, wih, bm, &hbuf[0][g][0], &hbuf[1][g][sub * 4]);
        rnn_step(x4.w, w, wih, bm, &hbuf[1][g][0], &hbuf[0][g][sub * 4]);
    }
    // T=784 (even number of ping-pongs): final h lives in buffer 0.

    // ---- fused classifier head: out[b][c] = h . W_lin[c] + b_lin[c] ----
    const float* hf = &hbuf[0][g][0];
#pragma unroll 1
    for (int c = sub; c < RC; c += GRP) {
        float acc = b_lin[c];
        const float* wl = W_lin + c * RH;
#pragma unroll
        for (int k = 0; k < RH; k++) acc = fmaf(hf[k], wl[k], acc);
        out[(size_t)b * RC + c] = acc;
    }
}

extern "C" void kernel_launch(void* const* d_in, const int* in_sizes, int n_in,
                              void* d_out, int out_size) {
    const float* inputs = (const float*)d_in[0];
    const float* W_ih   = (const float*)d_in[1];
    const float* W_hh   = (const float*)d_in[2];
    const float* b_mod  = (const float*)d_in[3];
    const float* W_lin  = (const float*)d_in[4];
    const float* b_lin  = (const float*)d_in[5];
    float* out = (float*)d_out;

    dim3 grid(RB / BPB);   // 1024 blocks
    dim3 block(TPB);       // 64 threads
    rnn_modrelu_kernel<<<grid, block>>>(inputs, W_ih, W_hh, b_mod,
                                        W_lin, b_lin, out);
}